// round 8
// baseline (speedup 1.0000x reference)
#include <cuda_runtime.h>
#include <cuda_bf16.h>

#define BB   512
#define HH   256
#define TT   365
#define NIN  10
#define NOUT 20
#define NBLK 128

__device__ unsigned g_bar;
__device__ float g_h0[2][BB * HH];
__device__ float g_h1[2][BB * HH];
__device__ float g_gh1[BB * 3 * HH];

// SMEM floats: As 64*260 + WsA 96*257 + WsB 48*257 + Wi0s 960 + xs 640 + biases 240
#define SMEM_FLOATS (64*260 + 96*257 + 48*257 + 960 + 640 + 96 + 96 + 48)
#define SMEM_BYTES  (SMEM_FLOATS * 4)

__global__ void gru_init() {
    int i = blockIdx.x * blockDim.x + threadIdx.x;
    int stride = gridDim.x * blockDim.x;
    for (int idx = i; idx < BB * HH; idx += stride) {
        g_h0[0][idx] = 0.f;
        g_h1[0][idx] = 0.f;
    }
    if (i == 0) g_bar = 0u;
}

__device__ __forceinline__ void gridbar(unsigned tgt) {
    __syncthreads();
    if (threadIdx.x == 0) {
        __threadfence();
        atomicAdd(&g_bar, 1u);
        while (*(volatile unsigned*)&g_bar < tgt) __nanosleep(64);
        __threadfence();
    }
    __syncthreads();
}

__device__ __forceinline__ float sigm(float v) { return 1.f / (1.f + expf(-v)); }

__global__ void __launch_bounds__(256, 1) gru_main(
    const float* __restrict__ x,
    const float* __restrict__ W_ih0, const float* __restrict__ W_hh0,
    const float* __restrict__ b_ih0, const float* __restrict__ b_hh0,
    const float* __restrict__ W_ih1, const float* __restrict__ W_hh1,
    const float* __restrict__ b_ih1, const float* __restrict__ b_hh1,
    const float* __restrict__ W_out, const float* __restrict__ b_out,
    float* __restrict__ out)
{
    extern __shared__ float smem[];
    float* As   = smem;                  // [64][260]
    float* WsA  = As   + 64 * 260;       // [96][257]
    float* WsB  = WsA  + 96 * 257;       // [48][257]
    float* Wi0s = WsB  + 48 * 257;       // [96][10]
    float* xs   = Wi0s + 960;            // [64][10]
    float* bihA = xs   + 640;            // [96]
    float* bhhA = bihA + 96;             // [96]
    float* bihB = bhhA + 96;             // [48]

    const int bid = blockIdx.x;
    const int tid = threadIdx.x;
    const bool isG0 = (bid < 64);

    const int bA = isG0 ? bid : bid - 64;
    const int mA = bA >> 3;              // 8 row tiles of 64
    const int jA = bA & 7;               // 8 col tiles of 32/gate
    const int mB = bid >> 4;             // 8 row tiles of 64
    const int jB = bid & 15;             // 16 col tiles of 16/gate

    const int tr = tid >> 4;             // 0..15 -> 4 rows each
    const int tc = tid & 15;

    // ---- one-time weight staging ----
    {
        const float* WA  = isG0 ? W_hh0 : W_hh1;
        const float* bhA = isG0 ? b_hh0 : b_hh1;
        for (int idx = tid; idx < 96 * 256; idx += 256) {
            int c = idx >> 8, k = idx & 255;
            int grow = (c >> 5) * 256 + jA * 32 + (c & 31);
            WsA[c * 257 + k] = WA[grow * 256 + k];
        }
        for (int idx = tid; idx < 48 * 256; idx += 256) {
            int c = idx >> 8, k = idx & 255;
            int grow = (c >> 4) * 256 + jB * 16 + (c & 15);
            WsB[c * 257 + k] = W_ih1[grow * 256 + k];
        }
        if (isG0) {
            for (int idx = tid; idx < 96 * NIN; idx += 256) {
                int c = idx / NIN, k = idx - c * NIN;
                int grow = (c >> 5) * 256 + jA * 32 + (c & 31);
                Wi0s[idx] = W_ih0[grow * NIN + k];
            }
        }
        if (tid < 96) {
            int grow = (tid >> 5) * 256 + jA * 32 + (tid & 31);
            bhhA[tid] = bhA[grow];
            if (isG0) bihA[tid] = b_ih0[grow];
        }
        if (tid < 48) {
            int grow = (tid >> 4) * 256 + jB * 16 + (tid & 15);
            bihB[tid] = b_ih1[grow];
        }
    }
    __syncthreads();

    unsigned bt = 0;

    for (int t = 0; t < TT; ++t) {
        const int cur = t & 1, nxt = cur ^ 1;

        // ===== Phase A: blocks 0-63: h0 update; blocks 64-127: gh1 =====
        {
            const float* hsrc = (isG0 ? g_h0[cur] : g_h1[cur]) + mA * 64 * HH;
            const float4* src4 = (const float4*)hsrc;
            #pragma unroll
            for (int i = 0; i < 16; ++i) {
                int f = tid + (i << 8);
                float4 v = __ldcg(src4 + f);
                int row = f >> 6, k4 = f & 63;
                *(float4*)(As + row * 260 + (k4 << 2)) = v;
            }
            if (isG0) {
                for (int idx = tid; idx < 64 * NIN; idx += 256) {
                    int row = idx / NIN, k = idx - row * NIN;
                    xs[idx] = __ldg(x + ((size_t)(mA * 64 + row) * TT + t) * NIN + k);
                }
            }
            __syncthreads();

            float acc[3][2][4];
            #pragma unroll
            for (int g = 0; g < 3; ++g)
                #pragma unroll
                for (int jj = 0; jj < 2; ++jj)
                    #pragma unroll
                    for (int i = 0; i < 4; ++i) acc[g][jj][i] = 0.f;

            const float* A0 = As + (tr << 2) * 260;
            const float* Wb = WsA + (tc * 2) * 257;

            #pragma unroll 2
            for (int k = 0; k < HH; ++k) {
                float a0 = A0[k], a1 = A0[260 + k], a2 = A0[520 + k], a3 = A0[780 + k];
                #pragma unroll
                for (int g = 0; g < 3; ++g) {
                    #pragma unroll
                    for (int jj = 0; jj < 2; ++jj) {
                        float w = Wb[g * (32 * 257) + jj * 257 + k];
                        acc[g][jj][0] = fmaf(a0, w, acc[g][jj][0]);
                        acc[g][jj][1] = fmaf(a1, w, acc[g][jj][1]);
                        acc[g][jj][2] = fmaf(a2, w, acc[g][jj][2]);
                        acc[g][jj][3] = fmaf(a3, w, acc[g][jj][3]);
                    }
                }
            }

            if (isG0) {
                #pragma unroll
                for (int jj = 0; jj < 2; ++jj) {
                    int jl = tc * 2 + jj;
                    int j  = jA * 32 + jl;
                    #pragma unroll
                    for (int i = 0; i < 4; ++i) {
                        int row = (tr << 2) + i;
                        float s0 = bihA[jl], s1 = bihA[32 + jl], s2 = bihA[64 + jl];
                        #pragma unroll
                        for (int k = 0; k < NIN; ++k) {
                            float xv = xs[row * NIN + k];
                            s0 = fmaf(xv, Wi0s[jl * NIN + k], s0);
                            s1 = fmaf(xv, Wi0s[(32 + jl) * NIN + k], s1);
                            s2 = fmaf(xv, Wi0s[(64 + jl) * NIN + k], s2);
                        }
                        float r = sigm(s0 + acc[0][jj][i] + bhhA[jl]);
                        float z = sigm(s1 + acc[1][jj][i] + bhhA[32 + jl]);
                        float n = tanhf(s2 + r * (acc[2][jj][i] + bhhA[64 + jl]));
                        float hp = As[row * 260 + j];
                        g_h0[nxt][(size_t)(mA * 64 + row) * HH + j] = (1.f - z) * n + z * hp;
                    }
                }
            } else {
                #pragma unroll
                for (int jj = 0; jj < 2; ++jj) {
                    int jl = tc * 2 + jj;
                    int j  = jA * 32 + jl;
                    #pragma unroll
                    for (int i = 0; i < 4; ++i) {
                        size_t b = (size_t)(mA * 64) + (tr << 2) + i;
                        g_gh1[b * 768 +       j] = acc[0][jj][i] + bhhA[jl];
                        g_gh1[b * 768 + 256 + j] = acc[1][jj][i] + bhhA[32 + jl];
                        g_gh1[b * 768 + 512 + j] = acc[2][jj][i] + bhhA[64 + jl];
                    }
                }
            }
        }
        bt += NBLK; gridbar(bt);

        // ===== Phase B: all blocks: gi1 = h0_new @ W_ih1^T, fuse gates =====
        {
            const float4* src4 = (const float4*)(g_h0[nxt] + mB * 64 * HH);
            #pragma unroll
            for (int i = 0; i < 16; ++i) {
                int f = tid + (i << 8);
                float4 v = __ldcg(src4 + f);
                int row = f >> 6, k4 = f & 63;
                *(float4*)(As + row * 260 + (k4 << 2)) = v;
            }
            __syncthreads();

            float acc[3][4];
            #pragma unroll
            for (int g = 0; g < 3; ++g)
                #pragma unroll
                for (int i = 0; i < 4; ++i) acc[g][i] = 0.f;

            const float* A0 = As + (tr << 2) * 260;
            const float* Wb = WsB + tc * 257;

            #pragma unroll 2
            for (int k = 0; k < HH; ++k) {
                float a0 = A0[k], a1 = A0[260 + k], a2 = A0[520 + k], a3 = A0[780 + k];
                #pragma unroll
                for (int g = 0; g < 3; ++g) {
                    float w = Wb[g * (16 * 257) + k];
                    acc[g][0] = fmaf(a0, w, acc[g][0]);
                    acc[g][1] = fmaf(a1, w, acc[g][1]);
                    acc[g][2] = fmaf(a2, w, acc[g][2]);
                    acc[g][3] = fmaf(a3, w, acc[g][3]);
                }
            }

            int j = jB * 16 + tc;
            #pragma unroll
            for (int i = 0; i < 4; ++i) {
                size_t b = (size_t)(mB * 64) + (tr << 2) + i;
                float ghr = __ldcg(&g_gh1[b * 768 +       j]);
                float ghz = __ldcg(&g_gh1[b * 768 + 256 + j]);
                float ghn = __ldcg(&g_gh1[b * 768 + 512 + j]);
                float r = sigm(acc[0][i] + bihB[tc]      + ghr);
                float z = sigm(acc[1][i] + bihB[16 + tc] + ghz);
                float n = tanhf(acc[2][i] + bihB[32 + tc] + r * ghn);
                float hp = __ldcg(&g_h1[cur][b * HH + j]);
                g_h1[nxt][b * HH + j] = (1.f - z) * n + z * hp;
            }
        }
        bt += NBLK; gridbar(bt);
        __syncthreads();
    }

    // ===== Epilogue: logits + softmax. Block handles 4 rows, warp per row =====
    const float* h1f = g_h1[TT & 1];
    int warp = tid >> 5, lane = tid & 31;
    if (warp < 4) {
        int row = bid * 4 + warp;
        float acc = 0.f;
        if (lane < NOUT) {
            acc = __ldg(b_out + lane);
            const float* wrow = W_out + lane * HH;
            const float* hrow = h1f + (size_t)row * HH;
            for (int k = 0; k < HH; ++k)
                acc = fmaf(__ldcg(hrow + k), __ldg(wrow + k), acc);
        }
        float v = (lane < NOUT) ? acc : -1e30f;
        float m = v;
        #pragma unroll
        for (int o = 16; o; o >>= 1) m = fmaxf(m, __shfl_xor_sync(0xffffffffu, m, o));
        float e = (lane < NOUT) ? expf(acc - m) : 0.f;
        float s = e;
        #pragma unroll
        for (int o = 16; o; o >>= 1) s += __shfl_xor_sync(0xffffffffu, s, o);
        if (lane < NOUT) out[(size_t)row * NOUT + lane] = e / s;
    }
}

extern "C" void kernel_launch(void* const* d_in, const int* in_sizes, int n_in,
                              void* d_out, int out_size) {
    const float* x     = (const float*)d_in[0];
    // d_in[1] = times (unused), d_in[2] = interpolation_method (unused)
    const float* W_ih0 = (const float*)d_in[3];
    const float* W_hh0 = (const float*)d_in[4];
    const float* b_ih0 = (const float*)d_in[5];
    const float* b_hh0 = (const float*)d_in[6];
    const float* W_ih1 = (const float*)d_in[7];
    const float* W_hh1 = (const float*)d_in[8];
    const float* b_ih1 = (const float*)d_in[9];
    const float* b_hh1 = (const float*)d_in[10];
    const float* W_out = (const float*)d_in[11];
    const float* b_out = (const float*)d_in[12];
    float* out = (float*)d_out;

    cudaFuncSetAttribute(gru_main, cudaFuncAttributeMaxDynamicSharedMemorySize, SMEM_BYTES);

    gru_init<<<128, 256>>>();
    gru_main<<<NBLK, 256, SMEM_BYTES>>>(x, W_ih0, W_hh0, b_ih0, b_hh0,
                                        W_ih1, W_hh1, b_ih1, b_hh1,
                                        W_out, b_out, out);
}

// round 9
// speedup vs baseline: 1.3872x; 1.3872x over previous
#include <cuda_runtime.h>
#include <cuda_bf16.h>

#define BB   512
#define HH   256
#define TT   365
#define NIN  10
#define NOUT 20
#define NBLK 128

__device__ unsigned g_bar;
__device__ float g_h0[2][BB * HH];
__device__ float g_h1[2][BB * HH];
__device__ float g_gh1[BB * 3 * HH];

// SMEM floats: As 64*260 + WsA 96*260 + WsB 48*260 + Wi0s 960 + xs 640 + biases 240
#define SMEM_FLOATS (64*260 + 96*260 + 48*260 + 960 + 640 + 96 + 96 + 48)
#define SMEM_BYTES  (SMEM_FLOATS * 4)

__global__ void gru_init() {
    int i = blockIdx.x * blockDim.x + threadIdx.x;
    int stride = gridDim.x * blockDim.x;
    for (int idx = i; idx < BB * HH; idx += stride) {
        g_h0[0][idx] = 0.f;
        g_h1[0][idx] = 0.f;
    }
    if (i == 0) g_bar = 0u;
}

__device__ __forceinline__ void gridbar(unsigned tgt) {
    __syncthreads();
    if (threadIdx.x == 0) {
        __threadfence();
        atomicAdd(&g_bar, 1u);
        while (*(volatile unsigned*)&g_bar < tgt) __nanosleep(32);
        __threadfence();
    }
    __syncthreads();
}

__device__ __forceinline__ float sigm(float v) { return 1.f / (1.f + expf(-v)); }

__global__ void __launch_bounds__(256, 1) gru_main(
    const float* __restrict__ x,
    const float* __restrict__ W_ih0, const float* __restrict__ W_hh0,
    const float* __restrict__ b_ih0, const float* __restrict__ b_hh0,
    const float* __restrict__ W_ih1, const float* __restrict__ W_hh1,
    const float* __restrict__ b_ih1, const float* __restrict__ b_hh1,
    const float* __restrict__ W_out, const float* __restrict__ b_out,
    float* __restrict__ out)
{
    extern __shared__ float smem[];
    float* As   = smem;                  // [64][260]
    float* WsA  = As   + 64 * 260;       // [96][260]
    float* WsB  = WsA  + 96 * 260;       // [48][260]
    float* Wi0s = WsB  + 48 * 260;       // [96][10]
    float* xs   = Wi0s + 960;            // [64][10]
    float* bihA = xs   + 640;            // [96]
    float* bhhA = bihA + 96;             // [96]
    float* bihB = bhhA + 96;             // [48]

    const int bid = blockIdx.x;
    const int tid = threadIdx.x;
    const bool isG0 = (bid < 64);

    const int bA = isG0 ? bid : bid - 64;
    const int mA = bA >> 3;              // 8 row tiles of 64
    const int jA = bA & 7;               // 8 col tiles of 32/gate
    const int mB = bid >> 4;             // 8 row tiles of 64
    const int jB = bid & 15;             // 16 col tiles of 16/gate

    const int tr = tid >> 4;             // 0..15 -> 4 rows each
    const int tc = tid & 15;             // 0..15

    // ---- one-time weight staging ----
    {
        const float* WA  = isG0 ? W_hh0 : W_hh1;
        const float* bhA = isG0 ? b_hh0 : b_hh1;
        for (int idx = tid; idx < 96 * 256; idx += 256) {
            int c = idx >> 8, k = idx & 255;
            int grow = (c >> 5) * 256 + jA * 32 + (c & 31);
            WsA[c * 260 + k] = WA[grow * 256 + k];
        }
        for (int idx = tid; idx < 48 * 256; idx += 256) {
            int c = idx >> 8, k = idx & 255;
            int grow = (c >> 4) * 256 + jB * 16 + (c & 15);
            WsB[c * 260 + k] = W_ih1[grow * 256 + k];
        }
        if (isG0) {
            for (int idx = tid; idx < 96 * NIN; idx += 256) {
                int c = idx / NIN, k = idx - c * NIN;
                int grow = (c >> 5) * 256 + jA * 32 + (c & 31);
                Wi0s[idx] = W_ih0[grow * NIN + k];
            }
        }
        if (tid < 96) {
            int grow = (tid >> 5) * 256 + jA * 32 + (tid & 31);
            bhhA[tid] = bhA[grow];
            if (isG0) bihA[tid] = b_ih0[grow];
        }
        if (tid < 48) {
            int grow = (tid >> 4) * 256 + jB * 16 + (tid & 15);
            bihB[tid] = b_ih1[grow];
        }
    }
    __syncthreads();

    unsigned bt = 0;

    for (int t = 0; t < TT; ++t) {
        const int cur = t & 1, nxt = cur ^ 1;

        // ===== Phase A: blocks 0-63: h0 update; blocks 64-127: gh1 =====
        {
            const float* hsrc = (isG0 ? g_h0[cur] : g_h1[cur]) + mA * 64 * HH;
            const float4* src4 = (const float4*)hsrc;
            #pragma unroll
            for (int i = 0; i < 16; ++i) {
                int f = tid + (i << 8);
                float4 v = __ldcg(src4 + f);
                int row = f >> 6, k4 = f & 63;
                *(float4*)(As + row * 260 + (k4 << 2)) = v;
            }
            if (isG0) {
                for (int idx = tid; idx < 64 * NIN; idx += 256) {
                    int row = idx / NIN, k = idx - row * NIN;
                    xs[idx] = __ldg(x + ((size_t)(mA * 64 + row) * TT + t) * NIN + k);
                }
            }
            __syncthreads();

            float acc[3][2][4];
            #pragma unroll
            for (int g = 0; g < 3; ++g)
                #pragma unroll
                for (int jj = 0; jj < 2; ++jj)
                    #pragma unroll
                    for (int i = 0; i < 4; ++i) acc[g][jj][i] = 0.f;

            const float* A0 = As + (tr << 2) * 260;
            const float* Wb = WsA + tc * 260;   // rows tc + 16*jj + 32*g

            #pragma unroll 2
            for (int k = 0; k < HH; k += 4) {
                float4 a0 = *(const float4*)(A0 + k);
                float4 a1 = *(const float4*)(A0 + 260 + k);
                float4 a2 = *(const float4*)(A0 + 520 + k);
                float4 a3 = *(const float4*)(A0 + 780 + k);
                #pragma unroll
                for (int g = 0; g < 3; ++g) {
                    #pragma unroll
                    for (int jj = 0; jj < 2; ++jj) {
                        float4 w = *(const float4*)(Wb + (g * 32 + jj * 16) * 260 + k);
                        float* a;
                        acc[g][jj][0] = fmaf(a0.x, w.x, fmaf(a0.y, w.y, fmaf(a0.z, w.z, fmaf(a0.w, w.w, acc[g][jj][0]))));
                        acc[g][jj][1] = fmaf(a1.x, w.x, fmaf(a1.y, w.y, fmaf(a1.z, w.z, fmaf(a1.w, w.w, acc[g][jj][1]))));
                        acc[g][jj][2] = fmaf(a2.x, w.x, fmaf(a2.y, w.y, fmaf(a2.z, w.z, fmaf(a2.w, w.w, acc[g][jj][2]))));
                        acc[g][jj][3] = fmaf(a3.x, w.x, fmaf(a3.y, w.y, fmaf(a3.z, w.z, fmaf(a3.w, w.w, acc[g][jj][3]))));
                        (void)a;
                    }
                }
            }

            if (isG0) {
                #pragma unroll
                for (int jj = 0; jj < 2; ++jj) {
                    int jl = tc + 16 * jj;
                    int j  = jA * 32 + jl;
                    #pragma unroll
                    for (int i = 0; i < 4; ++i) {
                        int row = (tr << 2) + i;
                        float s0 = bihA[jl], s1 = bihA[32 + jl], s2 = bihA[64 + jl];
                        #pragma unroll
                        for (int k = 0; k < NIN; ++k) {
                            float xv = xs[row * NIN + k];
                            s0 = fmaf(xv, Wi0s[jl * NIN + k], s0);
                            s1 = fmaf(xv, Wi0s[(32 + jl) * NIN + k], s1);
                            s2 = fmaf(xv, Wi0s[(64 + jl) * NIN + k], s2);
                        }
                        float r = sigm(s0 + acc[0][jj][i] + bhhA[jl]);
                        float z = sigm(s1 + acc[1][jj][i] + bhhA[32 + jl]);
                        float n = tanhf(s2 + r * (acc[2][jj][i] + bhhA[64 + jl]));
                        float hp = As[row * 260 + j];
                        g_h0[nxt][(size_t)(mA * 64 + row) * HH + j] = (1.f - z) * n + z * hp;
                    }
                }
            } else {
                #pragma unroll
                for (int jj = 0; jj < 2; ++jj) {
                    int jl = tc + 16 * jj;
                    int j  = jA * 32 + jl;
                    #pragma unroll
                    for (int i = 0; i < 4; ++i) {
                        size_t b = (size_t)(mA * 64) + (tr << 2) + i;
                        g_gh1[b * 768 +       j] = acc[0][jj][i] + bhhA[jl];
                        g_gh1[b * 768 + 256 + j] = acc[1][jj][i] + bhhA[32 + jl];
                        g_gh1[b * 768 + 512 + j] = acc[2][jj][i] + bhhA[64 + jl];
                    }
                }
            }
        }
        bt += NBLK; gridbar(bt);

        // ===== Phase B: all blocks: gi1 = h0_new @ W_ih1^T, fuse gates =====
        {
            const float4* src4 = (const float4*)(g_h0[nxt] + mB * 64 * HH);
            #pragma unroll
            for (int i = 0; i < 16; ++i) {
                int f = tid + (i << 8);
                float4 v = __ldcg(src4 + f);
                int row = f >> 6, k4 = f & 63;
                *(float4*)(As + row * 260 + (k4 << 2)) = v;
            }
            __syncthreads();

            float acc[3][4];
            #pragma unroll
            for (int g = 0; g < 3; ++g)
                #pragma unroll
                for (int i = 0; i < 4; ++i) acc[g][i] = 0.f;

            const float* A0 = As + (tr << 2) * 260;
            const float* Wb = WsB + tc * 260;   // rows tc + 16*g

            #pragma unroll 2
            for (int k = 0; k < HH; k += 4) {
                float4 a0 = *(const float4*)(A0 + k);
                float4 a1 = *(const float4*)(A0 + 260 + k);
                float4 a2 = *(const float4*)(A0 + 520 + k);
                float4 a3 = *(const float4*)(A0 + 780 + k);
                #pragma unroll
                for (int g = 0; g < 3; ++g) {
                    float4 w = *(const float4*)(Wb + g * 16 * 260 + k);
                    acc[g][0] = fmaf(a0.x, w.x, fmaf(a0.y, w.y, fmaf(a0.z, w.z, fmaf(a0.w, w.w, acc[g][0]))));
                    acc[g][1] = fmaf(a1.x, w.x, fmaf(a1.y, w.y, fmaf(a1.z, w.z, fmaf(a1.w, w.w, acc[g][1]))));
                    acc[g][2] = fmaf(a2.x, w.x, fmaf(a2.y, w.y, fmaf(a2.z, w.z, fmaf(a2.w, w.w, acc[g][2]))));
                    acc[g][3] = fmaf(a3.x, w.x, fmaf(a3.y, w.y, fmaf(a3.z, w.z, fmaf(a3.w, w.w, acc[g][3]))));
                }
            }

            int j = jB * 16 + tc;
            #pragma unroll
            for (int i = 0; i < 4; ++i) {
                size_t b = (size_t)(mB * 64) + (tr << 2) + i;
                float ghr = __ldcg(&g_gh1[b * 768 +       j]);
                float ghz = __ldcg(&g_gh1[b * 768 + 256 + j]);
                float ghn = __ldcg(&g_gh1[b * 768 + 512 + j]);
                float r = sigm(acc[0][i] + bihB[tc]      + ghr);
                float z = sigm(acc[1][i] + bihB[16 + tc] + ghz);
                float n = tanhf(acc[2][i] + bihB[32 + tc] + r * ghn);
                float hp = __ldcg(&g_h1[cur][b * HH + j]);
                g_h1[nxt][b * HH + j] = (1.f - z) * n + z * hp;
            }
        }
        bt += NBLK; gridbar(bt);
    }

    // ===== Epilogue: logits + softmax. Block handles 4 rows, warp per row =====
    const float* h1f = g_h1[TT & 1];
    int warp = tid >> 5, lane = tid & 31;
    if (warp < 4) {
        int row = bid * 4 + warp;
        float acc = 0.f;
        if (lane < NOUT) {
            acc = __ldg(b_out + lane);
            const float* wrow = W_out + lane * HH;
            const float* hrow = h1f + (size_t)row * HH;
            for (int k = 0; k < HH; ++k)
                acc = fmaf(__ldcg(hrow + k), __ldg(wrow + k), acc);
        }
        float v = (lane < NOUT) ? acc : -1e30f;
        float m = v;
        #pragma unroll
        for (int o = 16; o; o >>= 1) m = fmaxf(m, __shfl_xor_sync(0xffffffffu, m, o));
        float e = (lane < NOUT) ? expf(acc - m) : 0.f;
        float s = e;
        #pragma unroll
        for (int o = 16; o; o >>= 1) s += __shfl_xor_sync(0xffffffffu, s, o);
        if (lane < NOUT) out[(size_t)row * NOUT + lane] = e / s;
    }
}

extern "C" void kernel_launch(void* const* d_in, const int* in_sizes, int n_in,
                              void* d_out, int out_size) {
    const float* x     = (const float*)d_in[0];
    // d_in[1] = times (unused), d_in[2] = interpolation_method (unused)
    const float* W_ih0 = (const float*)d_in[3];
    const float* W_hh0 = (const float*)d_in[4];
    const float* b_ih0 = (const float*)d_in[5];
    const float* b_hh0 = (const float*)d_in[6];
    const float* W_ih1 = (const float*)d_in[7];
    const float* W_hh1 = (const float*)d_in[8];
    const float* b_ih1 = (const float*)d_in[9];
    const float* b_hh1 = (const float*)d_in[10];
    const float* W_out = (const float*)d_in[11];
    const float* b_out = (const float*)d_in[12];
    float* out = (float*)d_out;

    cudaFuncSetAttribute(gru_main, cudaFuncAttributeMaxDynamicSharedMemorySize, SMEM_BYTES);

    gru_init<<<128, 256>>>();
    gru_main<<<NBLK, 256, SMEM_BYTES>>>(x, W_ih0, W_hh0, b_ih0, b_hh0,
                                        W_ih1, W_hh1, b_ih1, b_hh1,
                                        W_out, b_out, out);
}